// round 1
// baseline (speedup 1.0000x reference)
#include <cuda_runtime.h>
#include <math.h>

#define B_ROWS   8192
#define M_DIM    512
#define N_DIM    2048
#define IN_COLS  4608   // M + 2N
#define OUT_COLS 8704   // IN_COLS + 2N
#define THETA    0.1f
#define KTH      103    // 103rd largest == sorted_asc[1945] == percentile(95, 'nearest') for n=2048

// Scratch (allocation-guard-safe device globals)
__device__ float g_gx [B_ROWS * N_DIM];
__device__ float g_res[B_ROWS * M_DIM];
__device__ float g_zk [B_ROWS * N_DIM];

// ---------------------------------------------------------------------------
// Kernel 1: passthrough copy of inputs into out[:, :4608] and gx = (1 + 0.5*exp(-|xk|)) * xk
// ---------------------------------------------------------------------------
__global__ void k_copy_gx(const float* __restrict__ in, float* __restrict__ out) {
    int b   = blockIdx.x;
    int tid = threadIdx.x;
    const float4* src = (const float4*)(in  + (size_t)b * IN_COLS);
    float4*       dst = (float4*)(out + (size_t)b * OUT_COLS);
    #pragma unroll 2
    for (int i = tid; i < IN_COLS / 4; i += 256) dst[i] = src[i];

    const float4* xk  = (const float4*)(in + (size_t)b * IN_COLS + 2560);
    float4*       gxr = (float4*)(g_gx + (size_t)b * N_DIM);
    #pragma unroll 2
    for (int i = tid; i < N_DIM / 4; i += 256) {
        float4 v = xk[i];
        float4 g;
        g.x = (1.0f + 0.5f * expf(-fabsf(v.x))) * v.x;
        g.y = (1.0f + 0.5f * expf(-fabsf(v.y))) * v.y;
        g.z = (1.0f + 0.5f * expf(-fabsf(v.z))) * v.z;
        g.w = (1.0f + 0.5f * expf(-fabsf(v.w))) * v.w;
        gxr[i] = g;
    }
}

// ---------------------------------------------------------------------------
// SGEMM tiling parameters: 128x128 block tile, BK=16, 256 threads, 8x8 per thread
// ---------------------------------------------------------------------------
#define BM 128
#define BN 128
#define BK 16
#define TM 8
#define TN 8

// GEMM1: res[b][m] = y[b][m] - sum_k gx[b][k] * A[m][k]      (K = 2048)
// Both operands are K-contiguous in global memory.
__global__ __launch_bounds__(256, 2)
void k_gemm1(const float* __restrict__ Amat, const float* __restrict__ in) {
    __shared__ float As[BK][BM];
    __shared__ float Bs[BK][BN];
    int tid  = threadIdx.x;
    int row0 = blockIdx.y * BM;   // batch rows
    int col0 = blockIdx.x * BN;   // output features (rows of A)
    int tx = tid % 16, ty = tid / 16;
    int lr = tid / 4;             // 0..63 (two rows: lr, lr+64)
    int lc = (tid % 4) * 4;       // 0,4,8,12

    float acc[TM][TN] = {};

    for (int k0 = 0; k0 < N_DIM; k0 += BK) {
        #pragma unroll
        for (int rr = 0; rr < 2; rr++) {
            int r = lr + rr * 64;
            float4 v = *(const float4*)(g_gx + (size_t)(row0 + r) * N_DIM + k0 + lc);
            As[lc + 0][r] = v.x; As[lc + 1][r] = v.y; As[lc + 2][r] = v.z; As[lc + 3][r] = v.w;
        }
        #pragma unroll
        for (int rr = 0; rr < 2; rr++) {
            int n = lr + rr * 64;
            float4 v = *(const float4*)(Amat + (size_t)(col0 + n) * N_DIM + k0 + lc);
            Bs[lc + 0][n] = v.x; Bs[lc + 1][n] = v.y; Bs[lc + 2][n] = v.z; Bs[lc + 3][n] = v.w;
        }
        __syncthreads();
        #pragma unroll
        for (int k = 0; k < BK; k++) {
            float ra[TM], rb[TN];
            #pragma unroll
            for (int i = 0; i < TM; i++) ra[i] = As[k][ty * TM + i];
            #pragma unroll
            for (int j = 0; j < TN; j++) rb[j] = Bs[k][tx * TN + j];
            #pragma unroll
            for (int i = 0; i < TM; i++)
                #pragma unroll
                for (int j = 0; j < TN; j++)
                    acc[i][j] += ra[i] * rb[j];
        }
        __syncthreads();
    }
    // epilogue: res = y - acc   (y = inputs[:, :512])
    #pragma unroll
    for (int i = 0; i < TM; i++) {
        int r = row0 + ty * TM + i;
        #pragma unroll
        for (int j = 0; j < TN; j++) {
            int c = col0 + tx * TN + j;
            g_res[(size_t)r * M_DIM + c] = in[(size_t)r * IN_COLS + c] - acc[i][j];
        }
    }
}

// GEMM2: zk[b][n] = gx[b][n] + 0.9 * sum_k res[b][k] * W[k][n]   (K = 512)
__global__ __launch_bounds__(256, 2)
void k_gemm2(const float* __restrict__ Wmat) {
    __shared__ float As[BK][BM];
    __shared__ float Bs[BK][BN];
    int tid  = threadIdx.x;
    int row0 = blockIdx.y * BM;
    int col0 = blockIdx.x * BN;
    int tx = tid % 16, ty = tid / 16;
    int lr = tid / 4;
    int lc = (tid % 4) * 4;
    int bk = tid / 32;            // 0..7 (two k's: bk, bk+8)
    int bn = (tid % 32) * 4;      // 0..124

    float acc[TM][TN] = {};

    for (int k0 = 0; k0 < M_DIM; k0 += BK) {
        #pragma unroll
        for (int rr = 0; rr < 2; rr++) {
            int r = lr + rr * 64;
            float4 v = *(const float4*)(g_res + (size_t)(row0 + r) * M_DIM + k0 + lc);
            As[lc + 0][r] = v.x; As[lc + 1][r] = v.y; As[lc + 2][r] = v.z; As[lc + 3][r] = v.w;
        }
        #pragma unroll
        for (int rr = 0; rr < 2; rr++) {
            int k = bk + rr * 8;
            *(float4*)&Bs[k][bn] =
                *(const float4*)(Wmat + (size_t)(k0 + k) * N_DIM + col0 + bn);
        }
        __syncthreads();
        #pragma unroll
        for (int k = 0; k < BK; k++) {
            float ra[TM], rb[TN];
            #pragma unroll
            for (int i = 0; i < TM; i++) ra[i] = As[k][ty * TM + i];
            #pragma unroll
            for (int j = 0; j < TN; j++) rb[j] = Bs[k][tx * TN + j];
            #pragma unroll
            for (int i = 0; i < TM; i++)
                #pragma unroll
                for (int j = 0; j < TN; j++)
                    acc[i][j] += ra[i] * rb[j];
        }
        __syncthreads();
    }
    #pragma unroll
    for (int i = 0; i < TM; i++) {
        int r = row0 + ty * TM + i;
        #pragma unroll
        for (int j = 0; j < TN; j++) {
            int c = col0 + tx * TN + j;
            size_t idx = (size_t)r * N_DIM + c;
            g_zk[idx] = g_gx[idx] + 0.9f * acc[i][j];
        }
    }
}

// ---------------------------------------------------------------------------
// Kernel 4: per-row exact k-th largest (bitwise radix select on |zk| bit
// patterns, register-resident) + shrink_ss + gating; writes cindex & output.
// ---------------------------------------------------------------------------
__global__ void k_shrink(const float* __restrict__ in, float* __restrict__ out) {
    int b   = blockIdx.x;
    int tid = threadIdx.x;
    __shared__ int scnt;

    const float* z = g_zk + (size_t)b * N_DIM;
    float    zf[8];
    unsigned vb[8];
    #pragma unroll
    for (int q = 0; q < 8; q++) {
        zf[q] = z[tid + q * 256];
        vb[q] = __float_as_uint(fabsf(zf[q]));
    }

    // k-th largest via MSB-down bitwise radix select (|z| >= 0, bit 31 == 0)
    unsigned prefix = 0u;
    int k = KTH;
    for (int bit = 30; bit >= 0; --bit) {
        if (tid == 0) scnt = 0;
        __syncthreads();
        unsigned mask = ~((1u << bit) - 1u);
        unsigned cand = prefix | (1u << bit);
        int c = 0;
        #pragma unroll
        for (int q = 0; q < 8; q++) c += ((vb[q] & mask) == cand);
        #pragma unroll
        for (int off = 16; off > 0; off >>= 1) c += __shfl_down_sync(0xffffffffu, c, off);
        if ((tid & 31) == 0 && c) atomicAdd(&scnt, c);
        __syncthreads();
        int cnt = scnt;
        if (cnt >= k) prefix = cand; else k -= cnt;
        __syncthreads();
    }
    float thres = __uint_as_float(prefix);

    const float* row_in = in + (size_t)b * IN_COLS;
    float* crow = out + (size_t)b * OUT_COLS + IN_COLS;          // cindex
    float* orow = crow + N_DIM;                                  // output

    #pragma unroll
    for (int q = 0; q < 8; q++) {
        int   i   = tid + q * 256;
        float zv  = zf[q];
        float az  = __uint_as_float(vb[q]);
        float ind = (az > THETA && az > thres) ? 1.0f : 0.0f;
        float ci  = 1.0f - ind;
        float soft = copysignf(fmaxf(az * ci - THETA, 0.0f), zv);
        float xt   = ind * zv + soft;
        float xkv  = row_in[2560 + i];
        float cprv = row_in[512 + i];
        float p1   = 1.0f / (fabsf(xt - xkv) + 0.1f);
        float g    = 1.0f - 0.5f * p1 * (THETA * cprv);
        float ov   = g * xt + (1.0f - g) * xkv;
        crow[i] = ci;
        orow[i] = ov;
    }
}

// ---------------------------------------------------------------------------
extern "C" void kernel_launch(void* const* d_in, const int* in_sizes, int n_in,
                              void* d_out, int out_size) {
    (void)in_sizes; (void)n_in; (void)out_size;
    const float* in = (const float*)d_in[0];   // (8192, 4608)
    const float* A  = (const float*)d_in[1];   // (512, 2048)
    const float* W  = (const float*)d_in[2];   // (512, 2048)
    float* out = (float*)d_out;                // (8192, 8704)

    k_copy_gx<<<B_ROWS, 256>>>(in, out);
    k_gemm1<<<dim3(M_DIM / BN, B_ROWS / BM), 256>>>(A, in);
    k_gemm2<<<dim3(N_DIM / BN, B_ROWS / BM), 256>>>(W);
    k_shrink<<<B_ROWS, 256>>>(in, out);
}